// round 3
// baseline (speedup 1.0000x reference)
#include <cuda_runtime.h>
#include <cuda_bf16.h>
#include <cstdint>

// Problem constants: e[8192,1024] f32, c[50257,1024] f32, targets[8192] i32 -> scalar f32
// NOTE: reference requests jnp.int64 but runs with JAX x64 disabled => targets are int32.
#define NTOK 8192
#define DK   1024
#define VV   50257
#define VPAD 50304          // 393 * 128
#define NVT  393            // number of 128-wide vocab tiles

#define BM 128
#define BN 128
#define BK 32
#define LDA 40              // smem row stride in bf16 elems (80B rows: conflict-free LDSM)

// -------- scratch (device globals; no allocation allowed) --------
__device__ __nv_bfloat16 g_e16[(size_t)NTOK * DK];   // 16 MB
__device__ __nv_bfloat16 g_c16[(size_t)VPAD * DK];   // ~103 MB (padded rows = 0)
__device__ float g_pmax[(size_t)NTOK * NVT];
__device__ float g_psum[(size_t)NTOK * NVT];
__device__ float g_nll[NTOK];

// ---------------- conversion ----------------
__global__ void cce_cvt_e(const float* __restrict__ e) {
    size_t n = (size_t)NTOK * DK;
    for (size_t i = blockIdx.x * (size_t)blockDim.x + threadIdx.x; i < n;
         i += (size_t)gridDim.x * blockDim.x)
        g_e16[i] = __float2bfloat16(e[i]);
}

__global__ void cce_cvt_c(const float* __restrict__ c) {
    size_t n  = (size_t)VPAD * DK;
    size_t nv = (size_t)VV * DK;
    for (size_t i = blockIdx.x * (size_t)blockDim.x + threadIdx.x; i < n;
         i += (size_t)gridDim.x * blockDim.x)
        g_c16[i] = (i < nv) ? __float2bfloat16(c[i]) : __float2bfloat16(0.0f);
}

// ---------------- PTX helpers ----------------
__device__ __forceinline__ uint32_t smem_u32(const void* p) {
    return (uint32_t)__cvta_generic_to_shared(p);
}

#define LDSM_X4(r0, r1, r2, r3, addr)                                          \
    asm volatile("ldmatrix.sync.aligned.m8n8.x4.shared.b16 {%0,%1,%2,%3}, [%4];" \
                 : "=r"(r0), "=r"(r1), "=r"(r2), "=r"(r3) : "r"(addr))

#define MMA_16816(d, a0, a1, a2, a3, b0, b1)                                   \
    asm volatile(                                                              \
        "mma.sync.aligned.m16n8k16.row.col.f32.bf16.bf16.f32 "                 \
        "{%0,%1,%2,%3}, {%4,%5,%6,%7}, {%8,%9}, {%0,%1,%2,%3};"                \
        : "+f"(d[0]), "+f"(d[1]), "+f"(d[2]), "+f"(d[3])                       \
        : "r"(a0), "r"(a1), "r"(a2), "r"(a3), "r"(b0), "r"(b1))

// ---------------- fused GEMM + partial LSE ----------------
// grid = (NTOK/BM, NVT); x = rowTile FASTEST so one wave shares the same c slice via L2.
// Block: 256 threads = 8 warps in a 4x2 (row x col) arrangement; each warp owns 32x64.
__global__ void __launch_bounds__(256) cce_gemm_lse() {
    __shared__ __align__(16) __nv_bfloat16 As[BM * LDA];
    __shared__ __align__(16) __nv_bfloat16 Bs[BN * LDA];
    __shared__ float combM[BM][2];
    __shared__ float combS[BM][2];

    const int rt = blockIdx.x, vt = blockIdx.y;
    const int row0 = rt * BM, col0 = vt * BN;
    const int tid  = threadIdx.x, lane = tid & 31, wid = tid >> 5;
    const int wr = wid & 3;   // warp row: 32 rows each
    const int wc = wid >> 2;  // warp col: 64 cols each
    const int gid = lane >> 2, tig = lane & 3;

    float acc[2][8][4];
#pragma unroll
    for (int i = 0; i < 2; i++)
#pragma unroll
        for (int j = 0; j < 8; j++)
#pragma unroll
            for (int k = 0; k < 4; k++) acc[i][j][k] = 0.0f;

    // ldmatrix lane addressing: lane%16 -> matrix row, lane/16 -> +8 cols (16B)
    const int lrow  = lane & 15;
    const int lcol8 = (lane >> 4) << 3;
    const uint32_t aBase = smem_u32(As) + (uint32_t)(((wr * 32 + lrow) * LDA + lcol8) * 2);
    const uint32_t bBase = smem_u32(Bs) + (uint32_t)(((wc * 64 + lrow) * LDA + lcol8) * 2);

    for (int kt = 0; kt < DK / BK; ++kt) {
        const int k0 = kt * BK;
        // Fill A (128x32) and B (128x32): 512 uint4 each, 2 per thread per tile.
#pragma unroll
        for (int i = 0; i < 2; i++) {
            int v  = tid + i * 256;
            int r  = v >> 2;
            int c8 = (v & 3) * 8;
            *(uint4*)(As + r * LDA + c8) =
                *(const uint4*)(g_e16 + (size_t)(row0 + r) * DK + k0 + c8);
            *(uint4*)(Bs + r * LDA + c8) =
                *(const uint4*)(g_c16 + (size_t)(col0 + r) * DK + k0 + c8);
        }
        __syncthreads();

#pragma unroll
        for (int kk = 0; kk < 2; kk++) {           // two k16 slabs of BK=32
            const uint32_t koff = (uint32_t)(kk * 16 * 2);  // bytes
            uint32_t a[2][4];
#pragma unroll
            for (int i = 0; i < 2; i++)
                LDSM_X4(a[i][0], a[i][1], a[i][2], a[i][3],
                        aBase + (uint32_t)(i * 16 * LDA * 2) + koff);
#pragma unroll
            for (int jj = 0; jj < 4; jj++) {
                uint32_t b0, b1, b2, b3;           // b0:n0-7/klo b1:n8-15/klo b2:n0-7/khi b3:n8-15/khi
                LDSM_X4(b0, b1, b2, b3, bBase + (uint32_t)(jj * 16 * LDA * 2) + koff);
#pragma unroll
                for (int i = 0; i < 2; i++) {
                    MMA_16816(acc[i][jj * 2 + 0], a[i][0], a[i][1], a[i][2], a[i][3], b0, b2);
                    MMA_16816(acc[i][jj * 2 + 1], a[i][0], a[i][1], a[i][2], a[i][3], b1, b3);
                }
            }
        }
        __syncthreads();
    }

    // ---- register-resident partial softmax over this 128x128 tile ----
    // acc[i][j]: c0,c1 -> row (wr*32 + i*16 + gid), cols 2*tig,2*tig+1 of n-tile j
    //            c2,c3 -> row +8.
    // Padded vocab cols (last tile) hold exact 0.0 logits; their contribution to the
    // merged LSE is ~exp(-M) with M = O(100) -> negligible, so no column guard.
#pragma unroll
    for (int i = 0; i < 2; i++) {
        float mA = -1e30f, mB = -1e30f;
#pragma unroll
        for (int j = 0; j < 8; j++) {
            mA = fmaxf(mA, fmaxf(acc[i][j][0], acc[i][j][1]));
            mB = fmaxf(mB, fmaxf(acc[i][j][2], acc[i][j][3]));
        }
        float sA = 0.0f, sB = 0.0f;
#pragma unroll
        for (int j = 0; j < 8; j++) {
            sA += __expf(acc[i][j][0] - mA) + __expf(acc[i][j][1] - mA);
            sB += __expf(acc[i][j][2] - mB) + __expf(acc[i][j][3] - mB);
        }
        // reduce across the 4 lanes of the quad (same gid, tig = 0..3)
#pragma unroll
        for (int off = 1; off <= 2; off <<= 1) {
            float mo = __shfl_xor_sync(0xffffffffu, mA, off);
            float so = __shfl_xor_sync(0xffffffffu, sA, off);
            float mn = fmaxf(mA, mo);
            sA = sA * __expf(mA - mn) + so * __expf(mo - mn);
            mA = mn;
            mo = __shfl_xor_sync(0xffffffffu, mB, off);
            so = __shfl_xor_sync(0xffffffffu, sB, off);
            mn = fmaxf(mB, mo);
            sB = sB * __expf(mB - mn) + so * __expf(mo - mn);
            mB = mn;
        }
        if (tig == 0) {
            int r = wr * 32 + i * 16 + gid;
            combM[r][wc] = mA;  combS[r][wc] = sA;
            combM[r + 8][wc] = mB;  combS[r + 8][wc] = sB;
        }
    }
    __syncthreads();

    if (tid < BM) {
        float m0 = combM[tid][0], m1 = combM[tid][1];
        float M  = fmaxf(m0, m1);
        float S  = combS[tid][0] * __expf(m0 - M) + combS[tid][1] * __expf(m1 - M);
        g_pmax[(size_t)(row0 + tid) * NVT + vt] = M;
        g_psum[(size_t)(row0 + tid) * NVT + vt] = S;
    }
}

// ---------------- per-row LSE merge + exact fp32 target logit ----------------
__global__ void cce_row_nll(const float* __restrict__ e, const float* __restrict__ c,
                            const int* __restrict__ tgt) {
    const int gw   = (blockIdx.x * blockDim.x + threadIdx.x) >> 5;
    const int lane = threadIdx.x & 31;
    if (gw >= NTOK) return;
    const int row = gw;

    float M = -1e30f;
    for (int j = lane; j < NVT; j += 32) M = fmaxf(M, g_pmax[(size_t)row * NVT + j]);
#pragma unroll
    for (int o = 16; o; o >>= 1) M = fmaxf(M, __shfl_xor_sync(0xffffffffu, M, o));

    float S = 0.0f;
    for (int j = lane; j < NVT; j += 32)
        S += g_psum[(size_t)row * NVT + j] * __expf(g_pmax[(size_t)row * NVT + j] - M);
#pragma unroll
    for (int o = 16; o; o >>= 1) S += __shfl_xor_sync(0xffffffffu, S, o);

    const float lse = M + logf(S);

    const int t = tgt[row];
    const bool valid = (t != -100);
    const int  st    = valid ? t : 0;
    const float* er = e + (size_t)row * DK;
    const float* cr = c + (size_t)st * DK;
    float dot = 0.0f;
    for (int k = lane; k < DK; k += 32) dot += er[k] * cr[k];
#pragma unroll
    for (int o = 16; o; o >>= 1) dot += __shfl_xor_sync(0xffffffffu, dot, o);

    if (lane == 0) g_nll[row] = valid ? (lse - dot) : 0.0f;
}

// ---------------- final mean ----------------
__global__ void cce_finalize(const int* __restrict__ tgt, float* __restrict__ out) {
    __shared__ float ss[256];
    __shared__ int   sc[256];
    float s = 0.0f;
    int   cnt = 0;
    for (int i = threadIdx.x; i < NTOK; i += 256) {
        s += g_nll[i];
        cnt += (tgt[i] != -100);
    }
    ss[threadIdx.x] = s;
    sc[threadIdx.x] = cnt;
    __syncthreads();
    for (int o = 128; o; o >>= 1) {
        if (threadIdx.x < o) {
            ss[threadIdx.x] += ss[threadIdx.x + o];
            sc[threadIdx.x] += sc[threadIdx.x + o];
        }
        __syncthreads();
    }
    if (threadIdx.x == 0) out[0] = ss[0] / fmaxf((float)sc[0], 1.0f);
}

extern "C" void kernel_launch(void* const* d_in, const int* in_sizes, int n_in,
                              void* d_out, int out_size) {
    const float* e  = (const float*)d_in[0];
    const float* c  = (const float*)d_in[1];
    const int*   tg = (const int*)d_in[2];   // int32 (JAX x64 disabled downcasts int64)
    float*       out = (float*)d_out;

    cce_cvt_e<<<4096, 256>>>(e);
    cce_cvt_c<<<8192, 256>>>(c);

    dim3 grid(NTOK / BM, NVT);  // x fastest => one wave shares the same c slice via L2
    cce_gemm_lse<<<grid, 256>>>();

    cce_row_nll<<<(NTOK * 32) / 256, 256>>>(e, c, tg);
    cce_finalize<<<1, 256>>>(tg, out);
}